// round 15
// baseline (speedup 1.0000x reference)
#include <cuda_runtime.h>
#include <cstdint>

// QuantumDotProductCircuit — single fused kernel.
//   ov(b) = a(b)^T M b(b),  score = |ov|^2, out = (1+score)/2
// a,b are real Kronecker product states from RY(tanh(x)*pi) on |0>,
// M = U_q^dagger U_k (16x16 complex) from W_q,W_k.
// The circuit simulation runs ONCE per block in SMEM (register-lean,
// cooperative, ~16 barriers) while the block's input LDGs are in flight,
// eliminating the separate prep kernel + second launch (~1.3us).

__device__ __forceinline__ unsigned long long pk2(float lo, float hi) {
    unsigned long long r;
    asm("mov.b64 %0, {%1, %2};" : "=l"(r) : "f"(lo), "f"(hi));
    return r;
}
__device__ __forceinline__ float2 upk2(unsigned long long v) {
    float2 r;
    asm("mov.b64 {%0, %1}, %2;" : "=f"(r.x), "=f"(r.y) : "l"(v));
    return r;
}
__device__ __forceinline__ unsigned long long fma2(unsigned long long a,
                                                   unsigned long long b,
                                                   unsigned long long c) {
    unsigned long long d;
    asm("fma.rn.f32x2 %0, %1, %2, %3;" : "=l"(d) : "l"(a), "l"(b), "l"(c));
    return d;
}
__device__ __forceinline__ unsigned long long add2(unsigned long long a,
                                                   unsigned long long b) {
    unsigned long long d;
    asm("add.rn.f32x2 %0, %1, %2;" : "=l"(d) : "l"(a), "l"(b));
    return d;
}

// fast tanh: (e^{2x}-1)/(e^{2x}+1), EX2 + RCP.approx. rel err ~1e-6.
__device__ __forceinline__ float fast_tanh(float x) {
    x = fminf(fmaxf(x, -9.0f), 9.0f);
    float e = __expf(2.0f * x);
    return __fdividef(e - 1.0f, e + 1.0f);
}

// ---------------------------------------------------------------------------
// Fused kernel: 256 elements per 256-thread block. launch_bounds(256,5)
// pins the 51-reg budget (R14's main body measured 48 regs / 17.9us).
// ---------------------------------------------------------------------------
__global__ void __launch_bounds__(256, 5) qdp_fused(
        const float4* __restrict__ q4, const float4* __restrict__ k4,
        const float* __restrict__ Wq, const float* __restrict__ Wk,
        float* __restrict__ out, int B) {
    __shared__ float2 Ush[2][16][16];   // [matrix][state t][column c]
    __shared__ float  Gsh[16][8];       // rot-gate coefficients (u00..u11 r/i)
    __shared__ ulonglong2 Msh[128];     // M interleaved (re,im), row-major

    const int tid = threadIdx.x;
    int idx = blockIdx.x * 256 + tid;
    if (idx >= B) idx = B - 1;

    // ---- 1) Issue input loads first (rows are 16 float4; take #0).
    //      Their ~600cyc DRAM latency hides under the circuit sim below.
    float4 qv = q4[(size_t)idx * 16];
    float4 kv = k4[(size_t)idx * 16];

    // ---- 2) Precompute the 16 Rot gates' 2x2 unitaries (16 threads).
    //      g = m*8 + layer*4 + w
    if (tid < 16) {
        int m = tid >> 3, layer = (tid >> 2) & 1, w = tid & 3;
        const float* W = m ? Wk : Wq;
        float phi = W[layer * 12 + w * 3 + 0];
        float th  = W[layer * 12 + w * 3 + 1];
        float om  = W[layer * 12 + w * 3 + 2];
        float cth, sth; __sincosf(0.5f * th, &sth, &cth);
        float sA, cA, sB, cB;
        __sincosf(0.5f * (phi + om), &sA, &cA);
        __sincosf(0.5f * (phi - om), &sB, &cB);
        Gsh[tid][0] =  cA * cth;  Gsh[tid][1] = -sA * cth;   // u00
        Gsh[tid][2] = -cB * sth;  Gsh[tid][3] = -sB * sth;   // u01
        Gsh[tid][4] =  cB * sth;  Gsh[tid][5] = -sB * sth;   // u10
        Gsh[tid][6] =  cA * cth;  Gsh[tid][7] =  sA * cth;   // u11
    }

    // ---- 3) Init U = identity (each column c starts as basis state c).
#pragma unroll
    for (int e = tid; e < 512; e += 256) {
        int m = e >> 8, t = (e >> 4) & 15, c = e & 15;
        Ush[m][t][c] = make_float2((t == c) ? 1.0f : 0.0f, 0.0f);
    }
    __syncthreads();

    // ---- 4) Apply the layered circuit cooperatively in SMEM.
    //      Wire w acts on index bit (3-w). One barrier per gate.
#pragma unroll
    for (int layer = 0; layer < 2; layer++) {
        // Rot gates: 256 pairs = 2 matrices x 16 cols x 8 state-pairs.
#pragma unroll
        for (int w = 0; w < 4; w++) {
            const int m = tid >> 7;
            const int gid = m * 8 + layer * 4 + w;
            const int b = 3 - w, st = 1 << b;
            const int c = (tid >> 3) & 15, p = tid & 7;
            const int s  = ((p >> b) << (b + 1)) | (p & (st - 1));
            const int s1 = s | st;
            float u00r = Gsh[gid][0], u00i = Gsh[gid][1];
            float u01r = Gsh[gid][2], u01i = Gsh[gid][3];
            float u10r = Gsh[gid][4], u10i = Gsh[gid][5];
            float u11r = Gsh[gid][6], u11i = Gsh[gid][7];
            float2 x = Ush[m][s][c], y = Ush[m][s1][c];
            float2 nx, ny;
            nx.x = u00r * x.x - u00i * x.y + u01r * y.x - u01i * y.y;
            nx.y = u00r * x.y + u00i * x.x + u01r * y.y + u01i * y.x;
            ny.x = u10r * x.x - u10i * x.y + u11r * y.x - u11i * y.y;
            ny.y = u10r * x.y + u10i * x.x + u11r * y.y + u11i * y.x;
            Ush[m][s][c] = nx;
            Ush[m][s1][c] = ny;
            __syncthreads();
        }
        // CNOT chain: 128 swap-pairs = 2 matrices x 16 cols x 4 pairs.
#pragma unroll
        for (int w = 0; w < 3; w++) {
            if (tid < 128) {
                const int m = tid >> 6;
                const int c = (tid >> 2) & 15, p = tid & 3;
                const int tb = 2 - w;
                const int cmv = 1 << (3 - w), tmv = 1 << tb;
                const int s0 = ((p >> tb) << (tb + 2)) | (p & (tmv - 1));
                const int s  = s0 | cmv;
                const int s1 = s | tmv;
                float2 x = Ush[m][s][c], y = Ush[m][s1][c];
                Ush[m][s][c] = y;
                Ush[m][s1][c] = x;
            }
            __syncthreads();
        }
    }

    // ---- 5) M[i][j] = sum_t conj(Uq[t][i]) * Uk[t][j]; one entry/thread.
    {
        const int i = tid >> 4, j = tid & 15;
        float mr = 0.0f, mi = 0.0f;
#pragma unroll
        for (int t = 0; t < 16; t++) {
            float2 uq = Ush[0][t][i];
            float2 uk = Ush[1][t][j];
            mr += uq.x * uk.x + uq.y * uk.y;
            mi += uq.x * uk.y - uq.y * uk.x;
        }
        float* gm = (float*)Msh;
        gm[2 * tid + 0] = mr;
        gm[2 * tid + 1] = mi;
    }
    __syncthreads();

    // ---- 6) Per-element math (R14 main body, measured 48 regs / 17.9us).
    const float HP = 1.5707963267948966f;  // pi/2 (half-angle scale)
    float cs[4], sn[4];
    __sincosf(fast_tanh(qv.x) * HP, &sn[0], &cs[0]);
    __sincosf(fast_tanh(qv.y) * HP, &sn[1], &cs[1]);
    __sincosf(fast_tanh(qv.z) * HP, &sn[2], &cs[2]);
    __sincosf(fast_tanh(qv.w) * HP, &sn[3], &cs[3]);
    float a01[4] = {cs[0]*cs[1], cs[0]*sn[1], sn[0]*cs[1], sn[0]*sn[1]};
    float a23[4] = {cs[2]*cs[3], cs[2]*sn[3], sn[2]*cs[3], sn[2]*sn[3]};

    __sincosf(fast_tanh(kv.x) * HP, &sn[0], &cs[0]);
    __sincosf(fast_tanh(kv.y) * HP, &sn[1], &cs[1]);
    __sincosf(fast_tanh(kv.z) * HP, &sn[2], &cs[2]);
    __sincosf(fast_tanh(kv.w) * HP, &sn[3], &cs[3]);
    float b01[4] = {cs[0]*cs[1], cs[0]*sn[1], sn[0]*cs[1], sn[0]*sn[1]};
    float b23[4] = {cs[2]*cs[3], cs[2]*sn[3], sn[2]*cs[3], sn[2]*sn[3]};

    unsigned long long bp[16];
#pragma unroll
    for (int j = 0; j < 16; j++) {
        float v = b01[j >> 2] * b23[j & 3];
        bp[j] = pk2(v, v);
    }

    // ov = sum_i av[i] * (sum_j M[i][j] * b[j]), packed (re,im) lanes
    unsigned long long ov0 = 0ULL, ov1 = 0ULL;
#pragma unroll
    for (int i = 0; i < 16; i++) {
        unsigned long long t0 = 0ULL, t1 = 0ULL;
#pragma unroll
        for (int jj = 0; jj < 8; jj++) {
            ulonglong2 m = Msh[i * 8 + jj];     // two complex entries
            t0 = fma2(m.x, bp[2 * jj + 0], t0);
            t1 = fma2(m.y, bp[2 * jj + 1], t1);
        }
        float avi = a01[i >> 2] * a23[i & 3];
        unsigned long long avp = pk2(avi, avi);
        unsigned long long s = add2(t0, t1);
        if (i & 1) ov1 = fma2(avp, s, ov1);
        else       ov0 = fma2(avp, s, ov0);
    }
    float2 o = upk2(add2(ov0, ov1));
    float score = o.x * o.x + o.y * o.y;
    out[idx] = fmaf(0.5f, score, 0.5f);
}

extern "C" void kernel_launch(void* const* d_in, const int* in_sizes, int n_in,
                              void* d_out, int out_size) {
    const float* q  = (const float*)d_in[0];
    const float* k  = (const float*)d_in[1];
    const float* Wq = (const float*)d_in[2];
    const float* Wk = (const float*)d_in[3];
    int B = in_sizes[0] / 64;
    int nblk = (B + 255) / 256;

    qdp_fused<<<nblk, 256>>>((const float4*)q, (const float4*)k,
                             Wq, Wk, (float*)d_out, B);
}

// round 16
// speedup vs baseline: 1.8517x; 1.8517x over previous
#include <cuda_runtime.h>
#include <cstdint>

// QuantumDotProductCircuit:
//   ov(b) = a(b)^T M b(b),  score = |ov|^2, out = (1+score)/2
// a,b are real Kronecker product states from RY(tanh(x)*pi) on |0>,
// M = U_q^dagger U_k is a fixed 16x16 complex matrix built from W_q,W_k.
// Two plain launches (PDL measured as a loss under graph replay).
// Prep uses __sincosf (fast path; prep contributes ~0.4us).
// Main = R1/R14 structure at 48 regs / 5 blocks/SM — measured 17.3-17.9us,
// at the strided-DRAM pattern floor (67MB @ ~3.9TB/s effective).

__device__ ulonglong2 g_M[128];  // 16x16 complex, interleaved (re,im), row-major

__device__ __forceinline__ unsigned long long pk2(float lo, float hi) {
    unsigned long long r;
    asm("mov.b64 %0, {%1, %2};" : "=l"(r) : "f"(lo), "f"(hi));
    return r;
}
__device__ __forceinline__ float2 upk2(unsigned long long v) {
    float2 r;
    asm("mov.b64 {%0, %1}, %2;" : "=f"(r.x), "=f"(r.y) : "l"(v));
    return r;
}
__device__ __forceinline__ unsigned long long fma2(unsigned long long a,
                                                   unsigned long long b,
                                                   unsigned long long c) {
    unsigned long long d;
    asm("fma.rn.f32x2 %0, %1, %2, %3;" : "=l"(d) : "l"(a), "l"(b), "l"(c));
    return d;
}
__device__ __forceinline__ unsigned long long add2(unsigned long long a,
                                                   unsigned long long b) {
    unsigned long long d;
    asm("add.rn.f32x2 %0, %1, %2;" : "=l"(d) : "l"(a), "l"(b));
    return d;
}

// fast tanh: (e^{2x}-1)/(e^{2x}+1), EX2 + RCP.approx. rel err ~1e-6.
__device__ __forceinline__ float fast_tanh(float x) {
    x = fminf(fmaxf(x, -9.0f), 9.0f);
    float e = __expf(2.0f * x);
    return __fdividef(e - 1.0f, e + 1.0f);
}

// ---------------------------------------------------------------------------
// Prep kernel: build U_q, U_k (16x16) by simulating the Rot+CNOT layers on
// each basis state, then M = U_q^dagger U_k. One block, 256 threads.
// Wire w maps to index bit (3-w) (reference reshape puts wire 0 as MSB).
// ---------------------------------------------------------------------------
__global__ void qdp_prep(const float* __restrict__ Wq, const float* __restrict__ Wk) {
    __shared__ float2 U[2][16][16];  // [matrix][row t][column c]
    int tid = threadIdx.x;

    if (tid < 32) {
        int m = tid >> 4;       // 0 = q, 1 = k
        int c = tid & 15;       // column = input basis state
        const float* W = m ? Wk : Wq;

        float vr[16], vi[16];
#pragma unroll
        for (int s = 0; s < 16; s++) { vr[s] = (s == c) ? 1.0f : 0.0f; vi[s] = 0.0f; }

#pragma unroll
        for (int layer = 0; layer < 2; layer++) {
#pragma unroll
            for (int w = 0; w < 4; w++) {
                float phi = W[layer * 12 + w * 3 + 0];
                float th  = W[layer * 12 + w * 3 + 1];
                float om  = W[layer * 12 + w * 3 + 2];
                float cth, sth; __sincosf(0.5f * th, &sth, &cth);
                float sA, cA, sB, cB;
                __sincosf(0.5f * (phi + om), &sA, &cA);
                __sincosf(0.5f * (phi - om), &sB, &cB);
                float u00r =  cA * cth, u00i = -sA * cth;
                float u01r = -cB * sth, u01i = -sB * sth;
                float u10r =  cB * sth, u10i = -sB * sth;
                float u11r =  cA * cth, u11i =  sA * cth;
                const int st = 8 >> w;
#pragma unroll
                for (int s = 0; s < 16; s++) {
                    if (!(s & st)) {
                        const int s1 = s | st;
                        float xr = vr[s], xi = vi[s], yr = vr[s1], yi = vi[s1];
                        vr[s]  = u00r * xr - u00i * xi + u01r * yr - u01i * yi;
                        vi[s]  = u00r * xi + u00i * xr + u01r * yi + u01i * yr;
                        vr[s1] = u10r * xr - u10i * xi + u11r * yr - u11i * yi;
                        vi[s1] = u10r * xi + u10i * xr + u11r * yi + u11i * yr;
                    }
                }
            }
#pragma unroll
            for (int w = 0; w < 3; w++) {
                const int cm = 8 >> w, tm = 4 >> w;
#pragma unroll
                for (int s = 0; s < 16; s++) {
                    if ((s & cm) && !(s & tm)) {
                        const int s1 = s | tm;
                        float tr = vr[s], ti = vi[s];
                        vr[s] = vr[s1]; vi[s] = vi[s1];
                        vr[s1] = tr;    vi[s1] = ti;
                    }
                }
            }
        }
#pragma unroll
        for (int t = 0; t < 16; t++) U[m][t][c] = make_float2(vr[t], vi[t]);
    }
    __syncthreads();

    // M[i][j] = sum_t conj(Uq[t][i]) * Uk[t][j]
    int i = tid >> 4, j = tid & 15;
    float mr = 0.0f, mi = 0.0f;
#pragma unroll
    for (int t = 0; t < 16; t++) {
        float2 q = U[0][t][i];
        float2 k = U[1][t][j];
        mr += q.x * k.x + q.y * k.y;
        mi += q.x * k.y - q.y * k.x;
    }
    float* gm = (float*)g_M;
    gm[2 * (i * 16 + j) + 0] = mr;
    gm[2 * (i * 16 + j) + 1] = mi;
}

// ---------------------------------------------------------------------------
// Main kernel: one thread per element, 256-thr blocks.
// launch_bounds(256, 5) pins the 51-reg budget (body compiles at 48)
// -> 5 blocks/SM, occ ~50% — the measured-best configuration.
// ---------------------------------------------------------------------------
__global__ void __launch_bounds__(256, 5) qdp_main(
        const float4* __restrict__ q4, const float4* __restrict__ k4,
        float* __restrict__ out, int B) {
    __shared__ ulonglong2 Msh[128];
    int tid = threadIdx.x;
    if (tid < 128) Msh[tid] = g_M[tid];
    __syncthreads();

    int idx = blockIdx.x * 256 + tid;
    if (idx >= B) idx = B - 1;

    // rows are 64 floats = 16 float4; we need float4 #0 of each row
    float4 qv = q4[(size_t)idx * 16];
    float4 kv = k4[(size_t)idx * 16];

    const float HP = 1.5707963267948966f;  // pi/2 (half-angle scale)
    float cs[4], sn[4];
    __sincosf(fast_tanh(qv.x) * HP, &sn[0], &cs[0]);
    __sincosf(fast_tanh(qv.y) * HP, &sn[1], &cs[1]);
    __sincosf(fast_tanh(qv.z) * HP, &sn[2], &cs[2]);
    __sincosf(fast_tanh(qv.w) * HP, &sn[3], &cs[3]);
    float a01[4] = {cs[0]*cs[1], cs[0]*sn[1], sn[0]*cs[1], sn[0]*sn[1]};
    float a23[4] = {cs[2]*cs[3], cs[2]*sn[3], sn[2]*cs[3], sn[2]*sn[3]};

    __sincosf(fast_tanh(kv.x) * HP, &sn[0], &cs[0]);
    __sincosf(fast_tanh(kv.y) * HP, &sn[1], &cs[1]);
    __sincosf(fast_tanh(kv.z) * HP, &sn[2], &cs[2]);
    __sincosf(fast_tanh(kv.w) * HP, &sn[3], &cs[3]);
    float b01[4] = {cs[0]*cs[1], cs[0]*sn[1], sn[0]*cs[1], sn[0]*sn[1]};
    float b23[4] = {cs[2]*cs[3], cs[2]*sn[3], sn[2]*cs[3], sn[2]*sn[3]};

    unsigned long long bp[16];
#pragma unroll
    for (int j = 0; j < 16; j++) {
        float v = b01[j >> 2] * b23[j & 3];
        bp[j] = pk2(v, v);
    }

    // ov = sum_i av[i] * (sum_j M[i][j] * b[j]), packed (re,im) lanes
    unsigned long long ov0 = 0ULL, ov1 = 0ULL;
#pragma unroll
    for (int i = 0; i < 16; i++) {
        unsigned long long t0 = 0ULL, t1 = 0ULL;
#pragma unroll
        for (int jj = 0; jj < 8; jj++) {
            ulonglong2 m = Msh[i * 8 + jj];     // two complex entries
            t0 = fma2(m.x, bp[2 * jj + 0], t0);
            t1 = fma2(m.y, bp[2 * jj + 1], t1);
        }
        float avi = a01[i >> 2] * a23[i & 3];
        unsigned long long avp = pk2(avi, avi);
        unsigned long long s = add2(t0, t1);
        if (i & 1) ov1 = fma2(avp, s, ov1);
        else       ov0 = fma2(avp, s, ov0);
    }
    float2 o = upk2(add2(ov0, ov1));
    float score = o.x * o.x + o.y * o.y;
    out[idx] = fmaf(0.5f, score, 0.5f);
}

extern "C" void kernel_launch(void* const* d_in, const int* in_sizes, int n_in,
                              void* d_out, int out_size) {
    const float* q  = (const float*)d_in[0];
    const float* k  = (const float*)d_in[1];
    const float* Wq = (const float*)d_in[2];
    const float* Wk = (const float*)d_in[3];
    int B = in_sizes[0] / 64;
    int nblk = (B + 255) / 256;

    qdp_prep<<<1, 256>>>(Wq, Wk);
    qdp_main<<<nblk, 256>>>((const float4*)q, (const float4*)k,
                            (float*)d_out, B);
}